// round 14
// baseline (speedup 1.0000x reference)
#include <cuda_runtime.h>

// ============================================================================
// QuantumLayer (4q, 2 layers, B=524288), Heisenberg picture.
// PERSISTENT GRID-STRIDE: 512 blocks x 256 threads x 4 samples (exact),
// single wave, block prep amortized 4x, next sample's LDG.128 prefetched
// behind current sample's compute (only the first load is exposed).
// tanh.approx encoding, wire-3-factored 36-term Pauli sum, float4 LDS consts.
// ============================================================================

__device__ __forceinline__ float tanha(float x) {
    float y; asm("tanh.approx.f32 %0, %1;" : "=f"(y) : "f"(x)); return y;
}

// Term table: bits0-3 = sin-selection S, bits4-7 = wire-set W, bit8 = sign.
__constant__ unsigned short c_tbl[36] = {
    0x0E0, 0x1E8, 0x0E4, 0x1EC, 0x1E2, 0x1EA, 0x1E6, 0x1EE,   // q0
    0x030, 0x032, 0x031, 0x033,                                 // q1
    0x070, 0x074, 0x172, 0x176, 0x171, 0x175, 0x173, 0x177,     // q2
    0x0F0, 0x0F8, 0x1F4, 0x1FC, 0x0F2, 0x1FA, 0x0F6, 0x1FE,     // q3
    0x0F1, 0x0F9, 0x1F5, 0x1FD, 0x0F3, 0x0FB, 0x0F7, 0x0FF
};

// s_enc[q] = {cos(phi_q), sin(phi_q), w0y_q, 0}; s_cf[0..8] = coefs 0..35.
__device__ __forceinline__ float4 eval_sample(const float4 xv,
                                              const float4* s_enc,
                                              const float4* s_cf) {
    const float PI = 3.14159265358979f;
    float xs[4] = {xv.x, xv.y, xv.z, xv.w};

    float X[4], Y[4], Z[4];
    #pragma unroll
    for (int q = 0; q < 4; q++) {
        float4 e = s_enc[q];
        float a = fmaf(tanha(xs[q]), PI, e.z);
        float sa, ca; __sincosf(a, &sa, &ca);
        X[q] = sa * e.x;
        Y[q] = sa * e.y;
        Z[q] = ca;
    }

    float y01 = Y[0]*Y[1], x01 = X[0]*X[1];
    float x12 = X[1]*X[2], y12 = Y[1]*Y[2];
    float z01 = Z[0]*Z[1], z12 = Z[1]*Z[2];
    float x02 = X[0]*X[2], z02 = Z[0]*Z[2];
    float yz01 = Y[0]*Z[1];
    float x01z2 = x01 * Z[2];
    float yzy   = yz01 * Y[2];
    float yx2   = y01 * X[2];

    // ---- <Z_0>: C0..C7 ----
    float4 cA = s_cf[0], cB = s_cf[1];
    float g0z = fmaf(cB.x, x12, cA.x * z01);
    float g0y = fmaf(cB.z, Y[1] * z02, cA.z * Y[2]);
    float g0x = fmaf(cB.y, yzy, cA.y * x01z2);
    float g0c = fmaf(cA.w, yx2, cB.w * X[0]);
    float a0 = fmaf(g0z, Z[3], fmaf(g0y, Y[3], fmaf(g0x, X[3], g0c)));

    // ---- <Z_1>: C8..C11 ----
    float4 cC = s_cf[2];
    float g1z = fmaf(cC.y, y12, cC.x * z02);
    float g1c = fmaf(cC.w, x02, cC.z * y01);
    float a1 = fmaf(g1z, Z[3], g1c);

    // ---- <Z_2>: C12..C19 ----
    float4 cD = s_cf[3], cE = s_cf[4];
    float g2z = fmaf(cD.z, Z[0] * x12, cD.x * Z[1]);
    float g2y = fmaf(cD.w, Y[1] * Z[2], cD.y * (Z[0] * Y[2]));
    float g2x = fmaf(cE.y, yx2, cE.w * X[0]);
    float g2c = fmaf(cE.x, x01z2, cE.z * yzy);
    float a2 = fmaf(g2z, Z[3], fmaf(g2y, Y[3], fmaf(g2x, X[3], g2c)));

    // ---- <Z_3>: C20..C35 ----
    float4 cF = s_cf[5], cG = s_cf[6], cH = s_cf[7], cI = s_cf[8];
    float g3z = fmaf(cF.w, (Y[0] * X[1]) * Y[2],
                fmaf(cG.w, X[0] * z12,
                fmaf(cH.x, y01, cI.x * x02)));
    float g3y = fmaf(cF.y, X[0] * Y[1],
                fmaf(cG.y, Y[0] * X[2],
                fmaf(cH.z, x01 * Y[2], cI.z * (yz01 * Z[2]))));
    float g3x = fmaf(cF.z, Z[1] * X[2],
                fmaf(cG.z, Z[0] * X[1],
                fmaf(cI.y, Z[0] * y12, cH.y * Z[2])));
    float g3c = fmaf(cF.x, z02,
                fmaf(cG.x, y12,
                fmaf(cH.w, z01 * X[2], cI.w * X[1])));
    float a3 = fmaf(g3z, Z[3], fmaf(g3y, Y[3], fmaf(g3x, X[3], g3c)));

    float4 o; o.x = a0; o.y = a1; o.z = a2; o.w = a3;
    return o;
}

#define NBLK  512
#define NTHR  256
#define NITER 4      // NBLK*NTHR*NITER == 524288 exactly

__global__ __launch_bounds__(NTHR)
void circuit_kernel(const float* __restrict__ x, const float* __restrict__ w,
                    float* __restrict__ out) {
    __shared__ float4 s_enc[4];
    __shared__ float4 s_cf[9];

    const int t = threadIdx.x;
    if (t < 4) {
        float sp, cp; __sincosf(w[2 * t + 1], &sp, &cp);
        s_enc[t] = make_float4(cp, sp, w[2 * t], 0.0f);
    }
    if (t < 36) {
        unsigned e = c_tbl[t];
        float v = 1.0f;
        #pragma unroll
        for (int j = 0; j < 4; j++) {
            if ((e >> (4 + j)) & 1) {
                float st, ct; __sincosf(w[8 + 2 * j], &st, &ct);
                v *= ((e >> j) & 1) ? st : ct;
            }
        }
        reinterpret_cast<float*>(s_cf)[t] = (e & 0x100) ? -v : v;
    }
    __syncthreads();

    const int stride = NBLK * NTHR;               // 131072
    int i = blockIdx.x * NTHR + t;

    const float4* x4 = reinterpret_cast<const float4*>(x);
    float4* o4 = reinterpret_cast<float4*>(out);

    float4 xv = x4[i];                            // only exposed load
    #pragma unroll
    for (int it = 0; it < NITER; it++) {
        float4 xn;
        if (it + 1 < NITER) xn = x4[i + stride];  // prefetch next sample
        float4 o = eval_sample(xv, s_enc, s_cf);
        o4[i] = o;
        i += stride;
        xv = xn;
    }
}

extern "C" void kernel_launch(void* const* d_in, const int* in_sizes, int n_in,
                              void* d_out, int out_size) {
    const float* x = (const float*)d_in[0];     // [B, 4]
    const float* w = (const float*)d_in[1];     // [2, 4, 2]
    float* out = (float*)d_out;                 // [B, 4]
    // B = 524288 = NBLK * NTHR * NITER (shape fixed by the problem).
    circuit_kernel<<<NBLK, NTHR>>>(x, w, out);
}

// round 15
// speedup vs baseline: 1.0036x; 1.0036x over previous
#include <cuda_runtime.h>

// ============================================================================
// QuantumLayer (4q, 2 layers, B=524288), Heisenberg picture.
// cp.async PIPELINE: 512 blocks x 256 threads x 4 samples. All four 16B
// global->shared copies are issued up front (MLP=4 with ZERO register cost),
// overlapping the block prep; compute drains the smem stages in order.
// tanh.approx encoding, wire-3-factored 36-term Pauli sum, float4 LDS consts.
// ============================================================================

__device__ __forceinline__ float tanha(float x) {
    float y; asm("tanh.approx.f32 %0, %1;" : "=f"(y) : "f"(x)); return y;
}

#define CP_ASYNC16(dst_u32, src)                                              \
    asm volatile("cp.async.ca.shared.global [%0], [%1], 16;"                  \
                 :: "r"(dst_u32), "l"(src) : "memory")
#define CP_COMMIT() asm volatile("cp.async.commit_group;" ::: "memory")
template <int N>
__device__ __forceinline__ void cp_wait() {
    asm volatile("cp.async.wait_group %0;" :: "n"(N) : "memory");
}

// Term table: bits0-3 = sin-selection S, bits4-7 = wire-set W, bit8 = sign.
__constant__ unsigned short c_tbl[36] = {
    0x0E0, 0x1E8, 0x0E4, 0x1EC, 0x1E2, 0x1EA, 0x1E6, 0x1EE,   // q0
    0x030, 0x032, 0x031, 0x033,                                 // q1
    0x070, 0x074, 0x172, 0x176, 0x171, 0x175, 0x173, 0x177,     // q2
    0x0F0, 0x0F8, 0x1F4, 0x1FC, 0x0F2, 0x1FA, 0x0F6, 0x1FE,     // q3
    0x0F1, 0x0F9, 0x1F5, 0x1FD, 0x0F3, 0x0FB, 0x0F7, 0x0FF
};

__device__ __forceinline__ float4 eval_sample(const float4 xv,
                                              const float4* s_enc,
                                              const float4* s_cf) {
    const float PI = 3.14159265358979f;
    float xs[4] = {xv.x, xv.y, xv.z, xv.w};

    float X[4], Y[4], Z[4];
    #pragma unroll
    for (int q = 0; q < 4; q++) {
        float4 e = s_enc[q];
        float a = fmaf(tanha(xs[q]), PI, e.z);
        float sa, ca; __sincosf(a, &sa, &ca);
        X[q] = sa * e.x;
        Y[q] = sa * e.y;
        Z[q] = ca;
    }

    float y01 = Y[0]*Y[1], x01 = X[0]*X[1];
    float x12 = X[1]*X[2], y12 = Y[1]*Y[2];
    float z01 = Z[0]*Z[1], z12 = Z[1]*Z[2];
    float x02 = X[0]*X[2], z02 = Z[0]*Z[2];
    float yz01 = Y[0]*Z[1];
    float x01z2 = x01 * Z[2];
    float yzy   = yz01 * Y[2];
    float yx2   = y01 * X[2];

    float4 cA = s_cf[0], cB = s_cf[1];
    float g0z = fmaf(cB.x, x12, cA.x * z01);
    float g0y = fmaf(cB.z, Y[1] * z02, cA.z * Y[2]);
    float g0x = fmaf(cB.y, yzy, cA.y * x01z2);
    float g0c = fmaf(cA.w, yx2, cB.w * X[0]);
    float a0 = fmaf(g0z, Z[3], fmaf(g0y, Y[3], fmaf(g0x, X[3], g0c)));

    float4 cC = s_cf[2];
    float g1z = fmaf(cC.y, y12, cC.x * z02);
    float g1c = fmaf(cC.w, x02, cC.z * y01);
    float a1 = fmaf(g1z, Z[3], g1c);

    float4 cD = s_cf[3], cE = s_cf[4];
    float g2z = fmaf(cD.z, Z[0] * x12, cD.x * Z[1]);
    float g2y = fmaf(cD.w, Y[1] * Z[2], cD.y * (Z[0] * Y[2]));
    float g2x = fmaf(cE.y, yx2, cE.w * X[0]);
    float g2c = fmaf(cE.x, x01z2, cE.z * yzy);
    float a2 = fmaf(g2z, Z[3], fmaf(g2y, Y[3], fmaf(g2x, X[3], g2c)));

    float4 cF = s_cf[5], cG = s_cf[6], cH = s_cf[7], cI = s_cf[8];
    float g3z = fmaf(cF.w, (Y[0] * X[1]) * Y[2],
                fmaf(cG.w, X[0] * z12,
                fmaf(cH.x, y01, cI.x * x02)));
    float g3y = fmaf(cF.y, X[0] * Y[1],
                fmaf(cG.y, Y[0] * X[2],
                fmaf(cH.z, x01 * Y[2], cI.z * (yz01 * Z[2]))));
    float g3x = fmaf(cF.z, Z[1] * X[2],
                fmaf(cG.z, Z[0] * X[1],
                fmaf(cI.y, Z[0] * y12, cH.y * Z[2])));
    float g3c = fmaf(cF.x, z02,
                fmaf(cG.x, y12,
                fmaf(cH.w, z01 * X[2], cI.w * X[1])));
    float a3 = fmaf(g3z, Z[3], fmaf(g3y, Y[3], fmaf(g3x, X[3], g3c)));

    float4 o; o.x = a0; o.y = a1; o.z = a2; o.w = a3;
    return o;
}

#define NBLK  512
#define NTHR  256
#define NITER 4      // NBLK*NTHR*NITER == 524288 exactly

__global__ __launch_bounds__(NTHR)
void circuit_kernel(const float* __restrict__ x, const float* __restrict__ w,
                    float* __restrict__ out) {
    __shared__ float4 s_enc[4];
    __shared__ float4 s_cf[9];
    __shared__ float4 s_buf[NITER][NTHR];

    const int t = threadIdx.x;
    const int stride = NBLK * NTHR;               // 131072
    const int base = blockIdx.x * NTHR + t;
    const float4* x4 = reinterpret_cast<const float4*>(x);

    // Issue all four global->shared copies FIRST (latency overlaps prep).
    #pragma unroll
    for (int s = 0; s < NITER; s++) {
        unsigned dst = (unsigned)__cvta_generic_to_shared(&s_buf[s][t]);
        CP_ASYNC16(dst, x4 + base + s * stride);
        CP_COMMIT();
    }

    // Block prep (runs while copies are in flight).
    if (t < 4) {
        float sp, cp; __sincosf(w[2 * t + 1], &sp, &cp);
        s_enc[t] = make_float4(cp, sp, w[2 * t], 0.0f);
    }
    if (t < 36) {
        unsigned e = c_tbl[t];
        float v = 1.0f;
        #pragma unroll
        for (int j = 0; j < 4; j++) {
            if ((e >> (4 + j)) & 1) {
                float st, ct; __sincosf(w[8 + 2 * j], &st, &ct);
                v *= ((e >> j) & 1) ? st : ct;
            }
        }
        reinterpret_cast<float*>(s_cf)[t] = (e & 0x100) ? -v : v;
    }
    __syncthreads();

    float4* o4 = reinterpret_cast<float4*>(out);

    // Drain stages in order; each thread reads only its own slot, so
    // cp.async.wait_group (per-thread completion) suffices — no barrier.
    cp_wait<3>();
    o4[base + 0 * stride] = eval_sample(s_buf[0][t], s_enc, s_cf);
    cp_wait<2>();
    o4[base + 1 * stride] = eval_sample(s_buf[1][t], s_enc, s_cf);
    cp_wait<1>();
    o4[base + 2 * stride] = eval_sample(s_buf[2][t], s_enc, s_cf);
    cp_wait<0>();
    o4[base + 3 * stride] = eval_sample(s_buf[3][t], s_enc, s_cf);
}

extern "C" void kernel_launch(void* const* d_in, const int* in_sizes, int n_in,
                              void* d_out, int out_size) {
    const float* x = (const float*)d_in[0];     // [B, 4]
    const float* w = (const float*)d_in[1];     // [2, 4, 2]
    float* out = (float*)d_out;                 // [B, 4]
    // B = 524288 = NBLK * NTHR * NITER (shape fixed by the problem).
    circuit_kernel<<<NBLK, NTHR>>>(x, w, out);
}

// round 17
// speedup vs baseline: 1.0294x; 1.0257x over previous
#include <cuda_runtime.h>

// ============================================================================
// QuantumLayer (4q, 2 layers, B=524288), Heisenberg picture.
// cp.async pipeline, re-shaped for occupancy: 1024 blocks x 256 threads x 2
// samples. __launch_bounds__(256,6) -> <=42 regs -> 6 blocks/SM resident
// (~48 warps/SM) to cover the MUFU dependency chains that cap issue.
// tanh.approx encoding, wire-3-factored 36-term Pauli sum, float4 LDS consts.
// ============================================================================

__device__ __forceinline__ float tanha(float x) {
    float y; asm("tanh.approx.f32 %0, %1;" : "=f"(y) : "f"(x)); return y;
}

#define CP_ASYNC16(dst_u32, src)                                              \
    asm volatile("cp.async.ca.shared.global [%0], [%1], 16;"                  \
                 :: "r"(dst_u32), "l"(src) : "memory")
#define CP_COMMIT() asm volatile("cp.async.commit_group;" ::: "memory")
template <int N>
__device__ __forceinline__ void cp_wait() {
    asm volatile("cp.async.wait_group %0;" :: "n"(N) : "memory");
}

// Term table: bits0-3 = sin-selection S, bits4-7 = wire-set W, bit8 = sign.
__constant__ unsigned short c_tbl[36] = {
    0x0E0, 0x1E8, 0x0E4, 0x1EC, 0x1E2, 0x1EA, 0x1E6, 0x1EE,   // q0
    0x030, 0x032, 0x031, 0x033,                                 // q1
    0x070, 0x074, 0x172, 0x176, 0x171, 0x175, 0x173, 0x177,     // q2
    0x0F0, 0x0F8, 0x1F4, 0x1FC, 0x0F2, 0x1FA, 0x0F6, 0x1FE,     // q3
    0x0F1, 0x0F9, 0x1F5, 0x1FD, 0x0F3, 0x0FB, 0x0F7, 0x0FF
};

__device__ __forceinline__ float4 eval_sample(const float4 xv,
                                              const float4* s_enc,
                                              const float4* s_cf) {
    const float PI = 3.14159265358979f;
    float xs[4] = {xv.x, xv.y, xv.z, xv.w};

    float X[4], Y[4], Z[4];
    #pragma unroll
    for (int q = 0; q < 4; q++) {
        float4 e = s_enc[q];
        float a = fmaf(tanha(xs[q]), PI, e.z);
        float sa, ca; __sincosf(a, &sa, &ca);
        X[q] = sa * e.x;
        Y[q] = sa * e.y;
        Z[q] = ca;
    }

    float y01 = Y[0]*Y[1], x01 = X[0]*X[1];
    float x12 = X[1]*X[2], y12 = Y[1]*Y[2];
    float z01 = Z[0]*Z[1], z12 = Z[1]*Z[2];
    float x02 = X[0]*X[2], z02 = Z[0]*Z[2];
    float yz01 = Y[0]*Z[1];
    float x01z2 = x01 * Z[2];
    float yzy   = yz01 * Y[2];
    float yx2   = y01 * X[2];

    float4 cA = s_cf[0], cB = s_cf[1];
    float g0z = fmaf(cB.x, x12, cA.x * z01);
    float g0y = fmaf(cB.z, Y[1] * z02, cA.z * Y[2]);
    float g0x = fmaf(cB.y, yzy, cA.y * x01z2);
    float g0c = fmaf(cA.w, yx2, cB.w * X[0]);
    float a0 = fmaf(g0z, Z[3], fmaf(g0y, Y[3], fmaf(g0x, X[3], g0c)));

    float4 cC = s_cf[2];
    float g1z = fmaf(cC.y, y12, cC.x * z02);
    float g1c = fmaf(cC.w, x02, cC.z * y01);
    float a1 = fmaf(g1z, Z[3], g1c);

    float4 cD = s_cf[3], cE = s_cf[4];
    float g2z = fmaf(cD.z, Z[0] * x12, cD.x * Z[1]);
    float g2y = fmaf(cD.w, Y[1] * Z[2], cD.y * (Z[0] * Y[2]));
    float g2x = fmaf(cE.y, yx2, cE.w * X[0]);
    float g2c = fmaf(cE.x, x01z2, cE.z * yzy);
    float a2 = fmaf(g2z, Z[3], fmaf(g2y, Y[3], fmaf(g2x, X[3], g2c)));

    float4 cF = s_cf[5], cG = s_cf[6], cH = s_cf[7], cI = s_cf[8];
    float g3z = fmaf(cF.w, (Y[0] * X[1]) * Y[2],
                fmaf(cG.w, X[0] * z12,
                fmaf(cH.x, y01, cI.x * x02)));
    float g3y = fmaf(cF.y, X[0] * Y[1],
                fmaf(cG.y, Y[0] * X[2],
                fmaf(cH.z, x01 * Y[2], cI.z * (yz01 * Z[2]))));
    float g3x = fmaf(cF.z, Z[1] * X[2],
                fmaf(cG.z, Z[0] * X[1],
                fmaf(cI.y, Z[0] * y12, cH.y * Z[2])));
    float g3c = fmaf(cF.x, z02,
                fmaf(cG.x, y12,
                fmaf(cH.w, z01 * X[2], cI.w * X[1])));
    float a3 = fmaf(g3z, Z[3], fmaf(g3y, Y[3], fmaf(g3x, X[3], g3c)));

    float4 o; o.x = a0; o.y = a1; o.z = a2; o.w = a3;
    return o;
}

#define NBLK  1024
#define NTHR  256
#define NITER 2      // NBLK*NTHR*NITER == 524288 exactly

__global__ __launch_bounds__(NTHR, 6)
void circuit_kernel(const float* __restrict__ x, const float* __restrict__ w,
                    float* __restrict__ out) {
    __shared__ float4 s_enc[4];
    __shared__ float4 s_cf[9];
    __shared__ float4 s_buf[NITER][NTHR];

    const int t = threadIdx.x;
    const int stride = NBLK * NTHR;               // 262144
    const int base = blockIdx.x * NTHR + t;
    const float4* x4 = reinterpret_cast<const float4*>(x);

    // Issue both global->shared copies FIRST (latency overlaps prep).
    #pragma unroll
    for (int s = 0; s < NITER; s++) {
        unsigned dst = (unsigned)__cvta_generic_to_shared(&s_buf[s][t]);
        CP_ASYNC16(dst, x4 + base + s * stride);
        CP_COMMIT();
    }

    // Block prep (runs while copies are in flight).
    if (t < 4) {
        float sp, cp; __sincosf(w[2 * t + 1], &sp, &cp);
        s_enc[t] = make_float4(cp, sp, w[2 * t], 0.0f);
    }
    if (t < 36) {
        unsigned e = c_tbl[t];
        float v = 1.0f;
        #pragma unroll
        for (int j = 0; j < 4; j++) {
            if ((e >> (4 + j)) & 1) {
                float st, ct; __sincosf(w[8 + 2 * j], &st, &ct);
                v *= ((e >> j) & 1) ? st : ct;
            }
        }
        reinterpret_cast<float*>(s_cf)[t] = (e & 0x100) ? -v : v;
    }
    __syncthreads();

    float4* o4 = reinterpret_cast<float4*>(out);

    // Each thread reads only its own slot -> per-thread wait_group suffices.
    cp_wait<1>();
    o4[base]          = eval_sample(s_buf[0][t], s_enc, s_cf);
    cp_wait<0>();
    o4[base + stride] = eval_sample(s_buf[1][t], s_enc, s_cf);
}

extern "C" void kernel_launch(void* const* d_in, const int* in_sizes, int n_in,
                              void* d_out, int out_size) {
    const float* x = (const float*)d_in[0];     // [B, 4]
    const float* w = (const float*)d_in[1];     // [2, 4, 2]
    float* out = (float*)d_out;                 // [B, 4]
    // B = 524288 = NBLK * NTHR * NITER (shape fixed by the problem).
    circuit_kernel<<<NBLK, NTHR>>>(x, w, out);
}